// round 9
// baseline (speedup 1.0000x reference)
#include <cuda_runtime.h>

// ReadGate, split-2 over M (kills wave-quantization tail) + lean combine:
//  k1 grid (B, 2): stream memory[b, half], no-max softmax partials -> scratch.
//  k2 grid 128 (one wave): stage oW once per block, combine/normalize/project
//     16 rows per block (4 concurrent x 4 iterations).

constexpr int Bn = 2048;
constexpr int Mn = 2048;
constexpr int Dn = 64;
constexpr int Vn = 64;
constexpr int THREADS = 256;
constexpr int NHW = 16;                        // half-warps per CTA
constexpr int UNROLL = 4;                      // m-rows per half-warp per iter
constexpr int SPLIT = 2;
constexpr int MCHUNK = Mn / SPLIT;             // 1024
constexpr int ITERS = MCHUNK / (NHW * UNROLL); // 16

__device__ float g_pooled[Bn * SPLIT * Dn];    // unnormalized partial pooled
__device__ float g_sum[Bn * SPLIT];            // partial exp-sums

__global__ __launch_bounds__(THREADS, 4)
void stream_kernel(const int* __restrict__ query,
                   const float* __restrict__ memory,
                   const float* __restrict__ emb,
                   const float* __restrict__ qW,
                   const float* __restrict__ qb)
{
    __shared__ float w_sh[Dn * 65];
    __shared__ float e_sh[Dn];
    __shared__ float q_sh[Dn];
    __shared__ float pooled_sh[NHW][Dn];
    __shared__ float sum_sh[NHW];

    const int b   = blockIdx.x;
    const int s   = blockIdx.y;
    const int tid = threadIdx.x;
    const int hw   = tid >> 4;
    const int lane = tid & 15;

    const float4* __restrict__ mrow =
        reinterpret_cast<const float4*>(memory + (size_t)b * (Mn * Dn)
                                               + (size_t)s * (MCHUNK * Dn)) + lane;

    // ---- issue first tile loads IMMEDIATELY (independent of q) ----
    float4 v[UNROLL];
    #pragma unroll
    for (int j = 0; j < UNROLL; ++j)
        v[j] = __ldcs(mrow + (size_t)(hw + j * NHW) * (Dn / 4));

    // ---- prologue overlapped with loads in flight: stage qW, compute q ----
    #pragma unroll
    for (int i = tid; i < Dn * Dn; i += THREADS)
        w_sh[(i >> 6) * 65 + (i & 63)] = qW[i];
    if (tid < Dn)
        e_sh[tid] = emb[query[b] * Dn + tid];
    __syncthreads();

    if (tid < Dn) {
        float acc = qb[tid];
        #pragma unroll
        for (int k = 0; k < Dn; ++k)
            acc = fmaf(e_sh[k], w_sh[tid * 65 + k], acc);
        q_sh[tid] = acc;
    }
    __syncthreads();

    const float q0 = q_sh[lane * 4 + 0];
    const float q1 = q_sh[lane * 4 + 1];
    const float q2 = q_sh[lane * 4 + 2];
    const float q3 = q_sh[lane * 4 + 3];

    float rsum = 0.f;
    float a0 = 0.f, a1 = 0.f, a2 = 0.f, a3 = 0.f;

    #pragma unroll 1
    for (int it = 0; it < ITERS; ++it) {
        // prefetch next iteration, clamped (last iter re-fetches L2-hot tile)
        const int nit = (it + 1 < ITERS) ? (it + 1) : (ITERS - 1);
        float4 nv[UNROLL];
        #pragma unroll
        for (int j = 0; j < UNROLL; ++j)
            nv[j] = __ldcs(mrow + (size_t)(hw + nit * (NHW * UNROLL) + j * NHW) * (Dn / 4));

        #pragma unroll
        for (int j = 0; j < UNROLL; ++j) {
            float sv = fmaf(v[j].x, q0, fmaf(v[j].y, q1, fmaf(v[j].z, q2, v[j].w * q3)));
            sv += __shfl_xor_sync(0xffffffffu, sv, 8);
            sv += __shfl_xor_sync(0xffffffffu, sv, 4);
            sv += __shfl_xor_sync(0xffffffffu, sv, 2);
            sv += __shfl_xor_sync(0xffffffffu, sv, 1);
            const float p = __expf(sv * 0.125f);   // no max-subtraction: |s/8| <~ 5
            rsum += p;
            a0 = fmaf(p, v[j].x, a0);
            a1 = fmaf(p, v[j].y, a1);
            a2 = fmaf(p, v[j].z, a2);
            a3 = fmaf(p, v[j].w, a3);
        }

        #pragma unroll
        for (int j = 0; j < UNROLL; ++j) v[j] = nv[j];
    }

    pooled_sh[hw][lane * 4 + 0] = a0;
    pooled_sh[hw][lane * 4 + 1] = a1;
    pooled_sh[hw][lane * 4 + 2] = a2;
    pooled_sh[hw][lane * 4 + 3] = a3;
    if (lane == 0) sum_sh[hw] = rsum;
    __syncthreads();

    if (tid < Dn) {
        float pl = 0.f;
        #pragma unroll
        for (int p = 0; p < NHW; ++p) pl += pooled_sh[p][tid];
        g_pooled[((size_t)b * SPLIT + s) * Dn + tid] = pl;
    }
    if (tid == 0) {
        float gs = 0.f;
        #pragma unroll
        for (int p = 0; p < NHW; ++p) gs += sum_sh[p];
        g_sum[b * SPLIT + s] = gs;
    }
}

// ---------------- combine + output projection ----------------
constexpr int ROWS_PER_BLK = 16;   // 128 blocks = exactly one wave
constexpr int CONC = 4;            // rows processed concurrently (256 thr / 64)

__global__ __launch_bounds__(THREADS)
void combine_kernel(const float* __restrict__ oW,
                    const float* __restrict__ ob,
                    float* __restrict__ out)
{
    __shared__ float w_sh[Dn * 65];
    __shared__ float p_sh[CONC][Dn];

    const int tid = threadIdx.x;
    const int r   = tid >> 6;       // concurrent row slot 0..3
    const int vv  = tid & 63;       // output index

    // stage oW once per block (vectorized loads, padded smem)
    const float4* oW4 = reinterpret_cast<const float4*>(oW);
    #pragma unroll
    for (int i = tid; i < Dn * Dn / 4; i += THREADS) {
        const float4 w = oW4[i];
        const int e = i * 4;
        float* dst = &w_sh[(e >> 6) * 65 + (e & 63)];
        dst[0] = w.x; dst[1] = w.y; dst[2] = w.z; dst[3] = w.w;
    }
    const float obv = ob[vv];
    __syncthreads();

    #pragma unroll
    for (int g = 0; g < ROWS_PER_BLK; g += CONC) {
        const int b = blockIdx.x * ROWS_PER_BLK + g + r;
        const float pl = g_pooled[((size_t)b * SPLIT + 0) * Dn + vv]
                       + g_pooled[((size_t)b * SPLIT + 1) * Dn + vv];
        const float gs = g_sum[b * SPLIT + 0] + g_sum[b * SPLIT + 1];
        p_sh[r][vv] = pl / gs;
        __syncthreads();

        float acc = obv;
        #pragma unroll
        for (int d = 0; d < Dn; ++d)
            acc = fmaf(p_sh[r][d], w_sh[vv * 65 + d], acc);
        out[(size_t)b * Vn + vv] = acc;
        __syncthreads();   // protect p_sh before next iteration's overwrite
    }
}

extern "C" void kernel_launch(void* const* d_in, const int* in_sizes, int n_in,
                              void* d_out, int out_size)
{
    const int*   query  = (const int*)  d_in[0];
    const float* memory = (const float*)d_in[1];
    const float* emb    = (const float*)d_in[2];
    const float* qW     = (const float*)d_in[3];
    const float* qb     = (const float*)d_in[4];
    const float* oW     = (const float*)d_in[5];
    const float* ob     = (const float*)d_in[6];
    float* out = (float*)d_out;

    stream_kernel<<<dim3(Bn, SPLIT), THREADS>>>(query, memory, emb, qW, qb);
    combine_kernel<<<Bn / ROWS_PER_BLK, THREADS>>>(oW, ob, out);
}

// round 10
// speedup vs baseline: 1.0142x; 1.0142x over previous
#include <cuda_runtime.h>

// ReadGate, split-2 over M (kills wave-quantization tail) + lean combine:
//  k1 grid (B, 2): stream memory[b, half], no-max softmax partials -> scratch.
//     CTA(0,0) additionally L2-prefetches oW so the combine kernel never
//     takes DRAM-cold misses on it.
//  k2 grid 512: pooled/gs loads issued before oW staging (latency overlap),
//     float4 staging, single barrier, 4 rows per block.

constexpr int Bn = 2048;
constexpr int Mn = 2048;
constexpr int Dn = 64;
constexpr int Vn = 64;
constexpr int THREADS = 256;
constexpr int NHW = 16;                        // half-warps per CTA
constexpr int UNROLL = 4;                      // m-rows per half-warp per iter
constexpr int SPLIT = 2;
constexpr int MCHUNK = Mn / SPLIT;             // 1024
constexpr int ITERS = MCHUNK / (NHW * UNROLL); // 16

__device__ float g_pooled[Bn * SPLIT * Dn];    // unnormalized partial pooled
__device__ float g_sum[Bn * SPLIT];            // partial exp-sums

__global__ __launch_bounds__(THREADS, 4)
void stream_kernel(const int* __restrict__ query,
                   const float* __restrict__ memory,
                   const float* __restrict__ emb,
                   const float* __restrict__ qW,
                   const float* __restrict__ qb,
                   const float* __restrict__ oW)
{
    __shared__ float w_sh[Dn * 65];
    __shared__ float e_sh[Dn];
    __shared__ float q_sh[Dn];
    __shared__ float pooled_sh[NHW][Dn];
    __shared__ float sum_sh[NHW];

    const int b   = blockIdx.x;
    const int s   = blockIdx.y;
    const int tid = threadIdx.x;
    const int hw   = tid >> 4;
    const int lane = tid & 15;

    const float4* __restrict__ mrow =
        reinterpret_cast<const float4*>(memory + (size_t)b * (Mn * Dn)
                                               + (size_t)s * (MCHUNK * Dn)) + lane;

    // ---- issue first tile loads IMMEDIATELY (independent of q) ----
    float4 v[UNROLL];
    #pragma unroll
    for (int j = 0; j < UNROLL; ++j)
        v[j] = __ldcs(mrow + (size_t)(hw + j * NHW) * (Dn / 4));

    // ---- warm oW into L2 for the combine kernel (one CTA, fire-and-forget) ----
    if (b == 0 && s == 0 && tid < 128)
        asm volatile("prefetch.global.L2 [%0];" :: "l"(oW + tid * 32));

    // ---- prologue overlapped with loads in flight: stage qW, compute q ----
    #pragma unroll
    for (int i = tid; i < Dn * Dn; i += THREADS)
        w_sh[(i >> 6) * 65 + (i & 63)] = qW[i];
    if (tid < Dn)
        e_sh[tid] = emb[query[b] * Dn + tid];
    __syncthreads();

    if (tid < Dn) {
        float acc = qb[tid];
        #pragma unroll
        for (int k = 0; k < Dn; ++k)
            acc = fmaf(e_sh[k], w_sh[tid * 65 + k], acc);
        q_sh[tid] = acc;
    }
    __syncthreads();

    const float q0 = q_sh[lane * 4 + 0];
    const float q1 = q_sh[lane * 4 + 1];
    const float q2 = q_sh[lane * 4 + 2];
    const float q3 = q_sh[lane * 4 + 3];

    float rsum = 0.f;
    float a0 = 0.f, a1 = 0.f, a2 = 0.f, a3 = 0.f;

    #pragma unroll 1
    for (int it = 0; it < ITERS; ++it) {
        // prefetch next iteration, clamped (last iter re-fetches L2-hot tile)
        const int nit = (it + 1 < ITERS) ? (it + 1) : (ITERS - 1);
        float4 nv[UNROLL];
        #pragma unroll
        for (int j = 0; j < UNROLL; ++j)
            nv[j] = __ldcs(mrow + (size_t)(hw + nit * (NHW * UNROLL) + j * NHW) * (Dn / 4));

        #pragma unroll
        for (int j = 0; j < UNROLL; ++j) {
            float sv = fmaf(v[j].x, q0, fmaf(v[j].y, q1, fmaf(v[j].z, q2, v[j].w * q3)));
            sv += __shfl_xor_sync(0xffffffffu, sv, 8);
            sv += __shfl_xor_sync(0xffffffffu, sv, 4);
            sv += __shfl_xor_sync(0xffffffffu, sv, 2);
            sv += __shfl_xor_sync(0xffffffffu, sv, 1);
            const float p = __expf(sv * 0.125f);   // no max-subtraction: |s/8| <~ 5
            rsum += p;
            a0 = fmaf(p, v[j].x, a0);
            a1 = fmaf(p, v[j].y, a1);
            a2 = fmaf(p, v[j].z, a2);
            a3 = fmaf(p, v[j].w, a3);
        }

        #pragma unroll
        for (int j = 0; j < UNROLL; ++j) v[j] = nv[j];
    }

    pooled_sh[hw][lane * 4 + 0] = a0;
    pooled_sh[hw][lane * 4 + 1] = a1;
    pooled_sh[hw][lane * 4 + 2] = a2;
    pooled_sh[hw][lane * 4 + 3] = a3;
    if (lane == 0) sum_sh[hw] = rsum;
    __syncthreads();

    if (tid < Dn) {
        float pl = 0.f;
        #pragma unroll
        for (int p = 0; p < NHW; ++p) pl += pooled_sh[p][tid];
        g_pooled[((size_t)b * SPLIT + s) * Dn + tid] = pl;
    }
    if (tid == 0) {
        float gs = 0.f;
        #pragma unroll
        for (int p = 0; p < NHW; ++p) gs += sum_sh[p];
        g_sum[b * SPLIT + s] = gs;
    }
}

// ---------------- combine + output projection ----------------
constexpr int CONC = 4;            // rows per block (256 thr / 64)

__global__ __launch_bounds__(THREADS)
void combine_kernel(const float* __restrict__ oW,
                    const float* __restrict__ ob,
                    float* __restrict__ out)
{
    __shared__ float w_sh[Dn * 65];
    __shared__ float p_sh[CONC][Dn];

    const int tid = threadIdx.x;
    const int r   = tid >> 6;       // row slot 0..3
    const int vv  = tid & 63;       // output index
    const int b   = blockIdx.x * CONC + r;

    // issue row-dependent loads FIRST (independent of oW staging -> overlap)
    const float pl0 = g_pooled[((size_t)b * SPLIT + 0) * Dn + vv];
    const float pl1 = g_pooled[((size_t)b * SPLIT + 1) * Dn + vv];
    const float gs  = g_sum[b * SPLIT + 0] + g_sum[b * SPLIT + 1];
    const float obv = ob[vv];

    // stage oW (vectorized, padded, L2-warm thanks to streamer prefetch)
    const float4* oW4 = reinterpret_cast<const float4*>(oW);
    #pragma unroll
    for (int i = tid; i < Dn * Dn / 4; i += THREADS) {
        const float4 w = oW4[i];
        const int e = i * 4;
        float* dst = &w_sh[(e >> 6) * 65 + (e & 63)];
        dst[0] = w.x; dst[1] = w.y; dst[2] = w.z; dst[3] = w.w;
    }

    p_sh[r][vv] = (pl0 + pl1) / gs;
    __syncthreads();

    float acc = obv;
    #pragma unroll
    for (int d = 0; d < Dn; ++d)
        acc = fmaf(p_sh[r][d], w_sh[vv * 65 + d], acc);
    out[(size_t)b * Vn + vv] = acc;
}

extern "C" void kernel_launch(void* const* d_in, const int* in_sizes, int n_in,
                              void* d_out, int out_size)
{
    const int*   query  = (const int*)  d_in[0];
    const float* memory = (const float*)d_in[1];
    const float* emb    = (const float*)d_in[2];
    const float* qW     = (const float*)d_in[3];
    const float* qb     = (const float*)d_in[4];
    const float* oW     = (const float*)d_in[5];
    const float* ob     = (const float*)d_in[6];
    float* out = (float*)d_out;

    stream_kernel<<<dim3(Bn, SPLIT), THREADS>>>(query, memory, emb, qW, qb, oW);
    combine_kernel<<<Bn / CONC, THREADS>>>(oW, ob, out);
}